// round 2
// baseline (speedup 1.0000x reference)
#include <cuda_runtime.h>
#include <math.h>

#define U_N 4000
#define P_N 4000
#define G_N 200
#define D   64
#define B_N 512
#define NUP (U_N + P_N)   // 8000
#define NGU (G_N + U_N)   // 4200
#define NGP (G_N + P_N)   // 4200

#define BM 64
#define BK 32

// ---------------- scratch (device globals; no allocation allowed) ----------
__device__ float g_Xup[NUP * D];
__device__ float g_Xgu[NGU * D];
__device__ float g_Xgp[NGP * D];
__device__ float g_Rup[NUP * D];   // GEMM accum -> propagated result in-place
__device__ float g_Rgu[NGU * D];
__device__ float g_Rgp[NGP * D];
__device__ float g_deg[NUP + NGU + NGP];
__device__ float g_uf[B_N * D];
__device__ float g_q [B_N * D];

// ---------------- init kernels ---------------------------------------------
__global__ void zero_bufs()
{
    int i = blockIdx.x * blockDim.x + threadIdx.x;
    if (i < NUP * D) g_Rup[i] = 0.f;
    if (i < NGU * D) { g_Rgu[i] = 0.f; g_Rgp[i] = 0.f; }
    if (i < NUP + NGU + NGP) g_deg[i] = 0.f;
}

__global__ void build_x(const float* __restrict__ ue,
                        const float* __restrict__ pe,
                        const float* __restrict__ ge)
{
    int i = blockIdx.x * blockDim.x + threadIdx.x;
    if (i < NUP * D) g_Xup[i] = (i < U_N * D) ? ue[i] : pe[i - U_N * D];
    if (i < NGU * D) {
        g_Xgu[i] = (i < G_N * D) ? ge[i] : ue[i - G_N * D];
        g_Xgp[i] = (i < G_N * D) ? ge[i] : pe[i - G_N * D];
    }
}

// ---------------- main propagation GEMM: R += A@X, deg += rowsum(A) --------
__global__ __launch_bounds__(256) void gemm_prop(
    const float* __restrict__ A, const float* __restrict__ X,
    float* __restrict__ R, float* __restrict__ deg,
    int n, int kPerSplit)
{
    __shared__ float As[BM][BK + 1];
    __shared__ float Bs[BK][D];

    const int tid = threadIdx.x;
    const int tx  = tid & 15;     // 16 col-groups * 4 cols = 64
    const int ty  = tid >> 4;     // 16 row-groups * 4 rows = 64
    const int rowBase = blockIdx.x * BM;
    const int kStart  = blockIdx.y * kPerSplit;
    const int kEnd    = min(kStart + kPerSplit, n);
    if (kStart >= n) return;

    float acc[4][4] = {};
    float dacc[4]   = {0.f, 0.f, 0.f, 0.f};

    for (int k0 = kStart; k0 < kEnd; k0 += BK) {
        // A tile: 64 x 32 (zero-filled past kEnd / n)
        #pragma unroll
        for (int it = 0; it < 2; it++) {
            int i  = tid + it * 256;       // 0..511 float4 slots
            int r  = i >> 3;
            int q4 = (i & 7) << 2;
            int gr = rowBase + r;
            int gc = k0 + q4;
            float4 v = make_float4(0.f, 0.f, 0.f, 0.f);
            if (gr < n) {
                if (gc + 3 < kEnd) {
                    v = *reinterpret_cast<const float4*>(&A[(size_t)gr * n + gc]);
                } else {
                    float t0 = (gc + 0 < kEnd) ? A[(size_t)gr * n + gc + 0] : 0.f;
                    float t1 = (gc + 1 < kEnd) ? A[(size_t)gr * n + gc + 1] : 0.f;
                    float t2 = (gc + 2 < kEnd) ? A[(size_t)gr * n + gc + 2] : 0.f;
                    float t3 = (gc + 3 < kEnd) ? A[(size_t)gr * n + gc + 3] : 0.f;
                    v = make_float4(t0, t1, t2, t3);
                }
            }
            As[r][q4 + 0] = v.x; As[r][q4 + 1] = v.y;
            As[r][q4 + 2] = v.z; As[r][q4 + 3] = v.w;
        }
        // X tile: 32 x 64 (zero-filled past kEnd)
        #pragma unroll
        for (int it = 0; it < 2; it++) {
            int i = tid + it * 256;
            int r = i >> 4;
            int c = (i & 15) << 2;
            int gk = k0 + r;
            float4 v = make_float4(0.f, 0.f, 0.f, 0.f);
            if (gk < kEnd) v = *reinterpret_cast<const float4*>(&X[(size_t)gk * D + c]);
            *reinterpret_cast<float4*>(&Bs[r][c]) = v;
        }
        __syncthreads();

        #pragma unroll
        for (int k = 0; k < BK; k++) {
            float a0 = As[ty * 4 + 0][k];
            float a1 = As[ty * 4 + 1][k];
            float a2 = As[ty * 4 + 2][k];
            float a3 = As[ty * 4 + 3][k];
            float4 b = *reinterpret_cast<const float4*>(&Bs[k][tx * 4]);
            if (tx == 0) { dacc[0] += a0; dacc[1] += a1; dacc[2] += a2; dacc[3] += a3; }
            acc[0][0] += a0 * b.x; acc[0][1] += a0 * b.y; acc[0][2] += a0 * b.z; acc[0][3] += a0 * b.w;
            acc[1][0] += a1 * b.x; acc[1][1] += a1 * b.y; acc[1][2] += a1 * b.z; acc[1][3] += a1 * b.w;
            acc[2][0] += a2 * b.x; acc[2][1] += a2 * b.y; acc[2][2] += a2 * b.z; acc[2][3] += a2 * b.w;
            acc[3][0] += a3 * b.x; acc[3][1] += a3 * b.y; acc[3][2] += a3 * b.z; acc[3][3] += a3 * b.w;
        }
        __syncthreads();
    }

    #pragma unroll
    for (int i = 0; i < 4; i++) {
        int gr = rowBase + ty * 4 + i;
        if (gr < n) {
            #pragma unroll
            for (int j = 0; j < 4; j++)
                atomicAdd(&R[gr * D + tx * 4 + j], acc[i][j]);
            if (tx == 0) atomicAdd(&deg[gr], dacc[i]);
        }
    }
}

// ---------------- epilogue: P = (X + R/max(deg,1e-8)) * 0.5 (in-place) -----
__global__ void epilogue(const float* __restrict__ X, float* __restrict__ R,
                         const float* __restrict__ deg, int n)
{
    int idx = blockIdx.x * blockDim.x + threadIdx.x;
    if (idx < n * D) {
        int row = idx >> 6;
        float d = fmaxf(deg[row], 1e-8f);
        R[idx] = (X[idx] + R[idx] / d) * 0.5f;
    }
}

// ---------------- user_feat gather + q = uf @ W -----------------------------
__global__ void uf_q_kernel(const int* __restrict__ uids,
                            const float* __restrict__ W,
                            float* __restrict__ out_uf)
{
    __shared__ float sh[D];
    int b = blockIdx.x;
    int d = threadIdx.x;
    int uid = uids[b];
    float v = 0.5f * (g_Rup[uid * D + d] + g_Rgu[(G_N + uid) * D + d]);
    sh[d] = v;
    g_uf[b * D + d] = v;
    out_uf[b * D + d] = v;
    __syncthreads();
    float acc = 0.f;
    #pragma unroll
    for (int k = 0; k < D; k++) acc += sh[k] * W[k * D + d];
    g_q[b * D + d] = acc;
}

// ---------------- fused attention scores ------------------------------------
#define SBU 32
#define SBP 64
#define SBK 32

__global__ __launch_bounds__(256) void score_kernel(float* __restrict__ scores)
{
    __shared__ float Qs[SBU][SBK];
    __shared__ float Us[SBU][SBK];
    __shared__ float I0[SBP][SBK + 1];
    __shared__ float I1[SBP][SBK + 1];

    const int tid = threadIdx.x;
    const int tx  = tid & 31;   // papers: 32 groups * 2 = 64
    const int ty  = tid >> 5;   // users:  8 groups * 4 = 32
    const int ub  = blockIdx.y * SBU;
    const int pb  = blockIdx.x * SBP;

    float l0[4][2] = {}, l1[4][2] = {}, d0[4][2] = {}, d1[4][2] = {};

    for (int kt = 0; kt < D; kt += SBK) {
        #pragma unroll
        for (int it = 0; it < 4; it++) {
            int i = tid + it * 256;          // 1024 elems
            int u = i >> 5, k = i & 31;
            Qs[u][k] = g_q [(ub + u) * D + kt + k];
            Us[u][k] = g_uf[(ub + u) * D + kt + k];
        }
        #pragma unroll
        for (int it = 0; it < 8; it++) {
            int i = tid + it * 256;          // 2048 elems
            int p = i >> 5, k = i & 31;
            int gp = pb + p;
            float v0 = 0.f, v1 = 0.f;
            if (gp < P_N) {
                v0 = g_Rup[(U_N + gp) * D + kt + k];
                v1 = g_Rgp[(G_N + gp) * D + kt + k];
            }
            I0[p][k] = v0;
            I1[p][k] = v1;
        }
        __syncthreads();

        #pragma unroll
        for (int k = 0; k < SBK; k++) {
            float qv[4], uv[4];
            #pragma unroll
            for (int i = 0; i < 4; i++) {
                qv[i] = Qs[ty * 4 + i][k];
                uv[i] = Us[ty * 4 + i][k];
            }
            float i0v[2], i1v[2];
            #pragma unroll
            for (int j = 0; j < 2; j++) {
                i0v[j] = I0[tx * 2 + j][k];
                i1v[j] = I1[tx * 2 + j][k];
            }
            #pragma unroll
            for (int i = 0; i < 4; i++)
                #pragma unroll
                for (int j = 0; j < 2; j++) {
                    l0[i][j] += qv[i] * i0v[j];
                    l1[i][j] += qv[i] * i1v[j];
                    d0[i][j] += uv[i] * i0v[j];
                    d1[i][j] += uv[i] * i1v[j];
                }
        }
        __syncthreads();
    }

    const float scale = 0.125f;   // 1/sqrt(64)
    #pragma unroll
    for (int i = 0; i < 4; i++) {
        int gu = ub + ty * 4 + i;
        #pragma unroll
        for (int j = 0; j < 2; j++) {
            int gp = pb + tx * 2 + j;
            if (gp < P_N) {
                float z  = (l0[i][j] - l1[i][j]) * scale;
                float a0 = 1.f / (1.f + expf(-z));
                scores[gu * P_N + gp] = a0 * d0[i][j] + (1.f - a0) * d1[i][j];
            }
        }
    }
}

// ---------------- launch -----------------------------------------------------
extern "C" void kernel_launch(void* const* d_in, const int* in_sizes, int n_in,
                              void* d_out, int out_size)
{
    const float* A_up = (const float*)d_in[0];
    const float* A_gu = (const float*)d_in[1];
    const float* A_gp = (const float*)d_in[2];
    const float* ue   = (const float*)d_in[3];
    const float* pe   = (const float*)d_in[4];
    const float* ge   = (const float*)d_in[5];
    const float* W    = (const float*)d_in[6];
    const int*   uids = (const int*)d_in[7];
    float* out = (float*)d_out;

    float *pXup, *pXgu, *pXgp, *pRup, *pRgu, *pRgp, *pdeg;
    cudaGetSymbolAddress((void**)&pXup, g_Xup);
    cudaGetSymbolAddress((void**)&pXgu, g_Xgu);
    cudaGetSymbolAddress((void**)&pXgp, g_Xgp);
    cudaGetSymbolAddress((void**)&pRup, g_Rup);
    cudaGetSymbolAddress((void**)&pRgu, g_Rgu);
    cudaGetSymbolAddress((void**)&pRgp, g_Rgp);
    cudaGetSymbolAddress((void**)&pdeg, g_deg);

    const int n1 = NUP * D;
    zero_bufs<<<(n1 + 255) / 256, 256>>>();
    build_x<<<(n1 + 255) / 256, 256>>>(ue, pe, ge);

    // u_p propagation GEMM
    {
        int n = NUP, splitk = 4;
        int kps = (((n + splitk - 1) / splitk) + BK - 1) / BK * BK;
        dim3 grid((n + BM - 1) / BM, splitk);
        gemm_prop<<<grid, 256>>>(A_up, pXup, pRup, pdeg, n, kps);
    }
    // g_u propagation GEMM
    {
        int n = NGU, splitk = 2;
        int kps = (((n + splitk - 1) / splitk) + BK - 1) / BK * BK;
        dim3 grid((n + BM - 1) / BM, splitk);
        gemm_prop<<<grid, 256>>>(A_gu, pXgu, pRgu, pdeg + NUP, n, kps);
    }
    // g_p propagation GEMM
    {
        int n = NGP, splitk = 2;
        int kps = (((n + splitk - 1) / splitk) + BK - 1) / BK * BK;
        dim3 grid((n + BM - 1) / BM, splitk);
        gemm_prop<<<grid, 256>>>(A_gp, pXgp, pRgp, pdeg + NUP + NGU, n, kps);
    }

    epilogue<<<(NUP * D + 255) / 256, 256>>>(pXup, pRup, pdeg, NUP);
    epilogue<<<(NGU * D + 255) / 256, 256>>>(pXgu, pRgu, pdeg + NUP, NGU);
    epilogue<<<(NGP * D + 255) / 256, 256>>>(pXgp, pRgp, pdeg + NUP + NGU, NGP);

    uf_q_kernel<<<B_N, D>>>(uids, W, out + (size_t)B_N * P_N);

    dim3 sg((P_N + SBP - 1) / SBP, B_N / SBU);
    score_kernel<<<sg, 256>>>(out);
}

// round 3
// speedup vs baseline: 3.0663x; 3.0663x over previous
#include <cuda_runtime.h>
#include <math.h>

#define U_N 4000
#define P_N 4000
#define G_N 200
#define D   64
#define B_N 512
#define NUP (U_N + P_N)   // 8000
#define NGU (G_N + U_N)   // 4200
#define NGP (G_N + P_N)   // 4200

// ---------------- scratch (device globals; no allocation allowed) ----------
__device__ float g_Xup[NUP * D];
__device__ float g_Xgu[NGU * D];
__device__ float g_Xgp[NGP * D];
__device__ float g_Rup[NUP * D];
__device__ float g_Rgu[NGU * D];
__device__ float g_Rgp[NGP * D];
__device__ float g_deg[NUP + NGU + NGP];
__device__ float g_uf[B_N * D];
__device__ float g_q [B_N * D];

// ---------------- init kernels ---------------------------------------------
__global__ void zero_bufs()
{
    int i = blockIdx.x * blockDim.x + threadIdx.x;
    if (i < NUP * D) g_Rup[i] = 0.f;
    if (i < NGU * D) { g_Rgu[i] = 0.f; g_Rgp[i] = 0.f; }
    if (i < NUP + NGU + NGP) g_deg[i] = 0.f;
}

__global__ void build_x(const float* __restrict__ ue,
                        const float* __restrict__ pe,
                        const float* __restrict__ ge)
{
    int i = blockIdx.x * blockDim.x + threadIdx.x;
    if (i < NUP * D) g_Xup[i] = (i < U_N * D) ? ue[i] : pe[i - U_N * D];
    if (i < NGU * D) {
        g_Xgu[i] = (i < G_N * D) ? ge[i] : ue[i - G_N * D];
        g_Xgp[i] = (i < G_N * D) ? ge[i] : pe[i - G_N * D];
    }
}

// ---------------- cp.async helpers -----------------------------------------
__device__ __forceinline__ void cp_async16(void* smem_dst, const void* gmem_src, int src_bytes)
{
    unsigned saddr = (unsigned)__cvta_generic_to_shared(smem_dst);
    asm volatile("cp.async.cg.shared.global [%0], [%1], 16, %2;\n"
                 :: "r"(saddr), "l"(gmem_src), "r"(src_bytes));
}
__device__ __forceinline__ void cp_commit() { asm volatile("cp.async.commit_group;\n"); }
template<int N> __device__ __forceinline__ void cp_wait()
{ asm volatile("cp.async.wait_group %0;\n" :: "n"(N)); }

// ---------------- fused tf32 MMA propagation GEMM ---------------------------
// R += A@X, deg += rowsum(A); three problems packed into one grid.
// Tile: BM=128 rows x 64 cols, BK=32. 256 thr = 8 warps, warp w owns rows 16w..16w+15.
#define BM 128
#define BK 32
#define ASTRIDE 36      // 128x36 floats (16B-aligned rows, conflict-free frag loads)
#define XSTRIDE 72      // 32x72 floats
#define ASZ (BM * ASTRIDE)        // 4608 floats
#define XSZ (BK * XSTRIDE)        // 2304 floats
#define STAGE (ASZ + XSZ)         // 6912 floats = 27648 B
#define SMEM_BYTES (2 * STAGE * 4)  // 55296 B

#define RT0 63
#define RT1 33
#define RT2 33
#define KS0 4
#define KS1 2
#define KS2 2
#define NB0 (RT0 * KS0)   // 252
#define NB1 (RT1 * KS1)   // 66
#define NB2 (RT2 * KS2)   // 66
#define NBLK (NB0 + NB1 + NB2)  // 384

__device__ __forceinline__ void load_tiles(
    float* As, float* Xs, const float* __restrict__ A, const float* __restrict__ X,
    int n, int rowBase, int k0, int tid)
{
    // A tile: 128 x 32 floats, 1024 float4 slots, 4 per thread
    #pragma unroll
    for (int i = 0; i < 4; i++) {
        int slot = tid + i * 256;
        int r  = slot >> 3;
        int c4 = (slot & 7) << 2;
        int gr = rowBase + r;
        int gc = k0 + c4;
        float* dst = &As[r * ASTRIDE + c4];
        int rem = n - gc;                 // n multiple of 4 -> rem multiple of 4
        int bytes = (gr < n) ? ((rem >= 4) ? 16 : (rem > 0 ? rem * 4 : 0)) : 0;
        if (bytes > 0) {
            cp_async16(dst, &A[(size_t)gr * n + gc], bytes);
        } else {
            *reinterpret_cast<float4*>(dst) = make_float4(0.f, 0.f, 0.f, 0.f);
        }
    }
    // X tile: 32 x 64 floats, 512 float4 slots, 2 per thread
    #pragma unroll
    for (int i = 0; i < 2; i++) {
        int slot = tid + i * 256;
        int kr = slot >> 4;
        int c4 = (slot & 15) << 2;
        int gk = k0 + kr;
        float* dst = &Xs[kr * XSTRIDE + c4];
        if (gk < n) {
            cp_async16(dst, &X[(size_t)gk * D + c4], 16);
        } else {
            *reinterpret_cast<float4*>(dst) = make_float4(0.f, 0.f, 0.f, 0.f);
        }
    }
}

extern "C" __global__ __launch_bounds__(256)
void gemm_all(const float* __restrict__ A0, const float* __restrict__ A1,
              const float* __restrict__ A2,
              float* __restrict__ X0, float* __restrict__ X1, float* __restrict__ X2,
              float* __restrict__ R0, float* __restrict__ R1, float* __restrict__ R2,
              float* __restrict__ degAll)
{
    extern __shared__ float smem[];
    const int tid  = threadIdx.x;
    const int lane = tid & 31;
    const int warp = tid >> 5;

    // ---- map block -> (problem, rowTile, ksplit) ----
    const float *A, *X; float *R, *deg;
    int n, rowTiles, kIters, kps, local;
    int b = blockIdx.x;
    if (b < NB0)            { A = A0; X = X0; R = R0; deg = degAll;             n = NUP; rowTiles = RT0; kIters = 250; kps = 63; local = b; }
    else if (b < NB0 + NB1) { A = A1; X = X1; R = R1; deg = degAll + NUP;       n = NGU; rowTiles = RT1; kIters = 132; kps = 66; local = b - NB0; }
    else                    { A = A2; X = X2; R = R2; deg = degAll + NUP + NGU; n = NGP; rowTiles = RT2; kIters = 132; kps = 66; local = b - NB0 - NB1; }

    const int rowTile = local % rowTiles;
    const int split   = local / rowTiles;
    const int rowBase = rowTile * BM;
    const int itStart = split * kps;
    const int itEnd   = min(kIters, itStart + kps);
    const int nIt     = itEnd - itStart;
    if (nIt <= 0) return;

    float* As[2] = { smem,          smem + STAGE };
    float* Xs[2] = { smem + ASZ,    smem + STAGE + ASZ };

    float c[8][4];
    #pragma unroll
    for (int nt = 0; nt < 8; nt++)
        #pragma unroll
        for (int j = 0; j < 4; j++) c[nt][j] = 0.f;

    float dsum = 0.f;                       // deg partial: row tid>>1, 16 cols
    const int degRowLoc = tid >> 1;
    const int degColLoc = (tid & 1) * 16;

    const int aR  = warp * 16 + (lane >> 2);   // fragment row within tile
    const int kc  = lane & 3;
    const int bN  = lane >> 2;

    load_tiles(As[0], Xs[0], A, X, n, rowBase, itStart * BK, tid);
    cp_commit();

    for (int i = 0; i < nIt; i++) {
        int cur = i & 1;
        if (i + 1 < nIt)
            load_tiles(As[cur ^ 1], Xs[cur ^ 1], A, X, n, rowBase, (itStart + i + 1) * BK, tid);
        cp_commit();
        cp_wait<1>();
        __syncthreads();

        const float* Ac = As[cur];
        const float* Xc = Xs[cur];

        // degree partial sums (rowsum of the A tile)
        {
            const float4* p = reinterpret_cast<const float4*>(&Ac[degRowLoc * ASTRIDE + degColLoc]);
            #pragma unroll
            for (int j = 0; j < 4; j++) {
                float4 v = p[j];
                dsum += (v.x + v.y) + (v.z + v.w);
            }
        }

        // 4 k-steps of 8
        #pragma unroll
        for (int ks = 0; ks < 4; ks++) {
            int kb = ks * 8;
            unsigned a0 = __float_as_uint(Ac[aR       * ASTRIDE + kb + kc]);
            unsigned a1 = __float_as_uint(Ac[(aR + 8) * ASTRIDE + kb + kc]);
            unsigned a2 = __float_as_uint(Ac[aR       * ASTRIDE + kb + kc + 4]);
            unsigned a3 = __float_as_uint(Ac[(aR + 8) * ASTRIDE + kb + kc + 4]);
            #pragma unroll
            for (int nt = 0; nt < 8; nt++) {
                unsigned b0 = __float_as_uint(Xc[(kb + kc)     * XSTRIDE + nt * 8 + bN]);
                unsigned b1 = __float_as_uint(Xc[(kb + kc + 4) * XSTRIDE + nt * 8 + bN]);
                asm volatile(
                    "mma.sync.aligned.m16n8k8.row.col.f32.tf32.tf32.f32 "
                    "{%0,%1,%2,%3}, {%4,%5,%6,%7}, {%8,%9}, {%0,%1,%2,%3};\n"
                    : "+f"(c[nt][0]), "+f"(c[nt][1]), "+f"(c[nt][2]), "+f"(c[nt][3])
                    : "r"(a0), "r"(a1), "r"(a2), "r"(a3), "r"(b0), "r"(b1));
            }
        }
        __syncthreads();
    }

    // ---- epilogue: atomic accumulate (split-K) ----
    {
        int gr = rowBase + degRowLoc;
        if (gr < n) atomicAdd(&deg[gr], dsum);
    }
    const int r0 = rowBase + warp * 16 + (lane >> 2);
    const int ccBase = (lane & 3) * 2;
    #pragma unroll
    for (int nt = 0; nt < 8; nt++) {
        int cc = nt * 8 + ccBase;
        if (r0 < n) {
            atomicAdd(&R[r0 * D + cc],     c[nt][0]);
            atomicAdd(&R[r0 * D + cc + 1], c[nt][1]);
        }
        if (r0 + 8 < n) {
            atomicAdd(&R[(r0 + 8) * D + cc],     c[nt][2]);
            atomicAdd(&R[(r0 + 8) * D + cc + 1], c[nt][3]);
        }
    }
}

// ---------------- epilogue: P = (X + R/max(deg,1e-8)) * 0.5 (in-place) -----
__global__ void epilogue(const float* __restrict__ X, float* __restrict__ R,
                         const float* __restrict__ deg, int n)
{
    int idx = blockIdx.x * blockDim.x + threadIdx.x;
    if (idx < n * D) {
        int row = idx >> 6;
        float d = fmaxf(deg[row], 1e-8f);
        R[idx] = (X[idx] + R[idx] / d) * 0.5f;
    }
}

// ---------------- user_feat gather + q = uf @ W -----------------------------
__global__ void uf_q_kernel(const int* __restrict__ uids,
                            const float* __restrict__ W,
                            float* __restrict__ out_uf)
{
    __shared__ float sh[D];
    int b = blockIdx.x;
    int d = threadIdx.x;
    int uid = uids[b];
    float v = 0.5f * (g_Rup[uid * D + d] + g_Rgu[(G_N + uid) * D + d]);
    sh[d] = v;
    g_uf[b * D + d] = v;
    out_uf[b * D + d] = v;
    __syncthreads();
    float acc = 0.f;
    #pragma unroll
    for (int k = 0; k < D; k++) acc += sh[k] * W[k * D + d];
    g_q[b * D + d] = acc;
}

// ---------------- fused attention scores ------------------------------------
#define SBU 32
#define SBP 64
#define SBK 32

__global__ __launch_bounds__(256) void score_kernel(float* __restrict__ scores)
{
    __shared__ float Qs[SBU][SBK];
    __shared__ float Us[SBU][SBK];
    __shared__ float I0[SBP][SBK + 1];
    __shared__ float I1[SBP][SBK + 1];

    const int tid = threadIdx.x;
    const int tx  = tid & 31;
    const int ty  = tid >> 5;
    const int ub  = blockIdx.y * SBU;
    const int pb  = blockIdx.x * SBP;

    float l0[4][2] = {}, l1[4][2] = {}, d0[4][2] = {}, d1[4][2] = {};

    for (int kt = 0; kt < D; kt += SBK) {
        #pragma unroll
        for (int it = 0; it < 4; it++) {
            int i = tid + it * 256;
            int u = i >> 5, k = i & 31;
            Qs[u][k] = g_q [(ub + u) * D + kt + k];
            Us[u][k] = g_uf[(ub + u) * D + kt + k];
        }
        #pragma unroll
        for (int it = 0; it < 8; it++) {
            int i = tid + it * 256;
            int p = i >> 5, k = i & 31;
            int gp = pb + p;
            float v0 = 0.f, v1 = 0.f;
            if (gp < P_N) {
                v0 = g_Rup[(U_N + gp) * D + kt + k];
                v1 = g_Rgp[(G_N + gp) * D + kt + k];
            }
            I0[p][k] = v0;
            I1[p][k] = v1;
        }
        __syncthreads();

        #pragma unroll
        for (int k = 0; k < SBK; k++) {
            float qv[4], uv[4];
            #pragma unroll
            for (int i = 0; i < 4; i++) {
                qv[i] = Qs[ty * 4 + i][k];
                uv[i] = Us[ty * 4 + i][k];
            }
            float i0v[2], i1v[2];
            #pragma unroll
            for (int j = 0; j < 2; j++) {
                i0v[j] = I0[tx * 2 + j][k];
                i1v[j] = I1[tx * 2 + j][k];
            }
            #pragma unroll
            for (int i = 0; i < 4; i++)
                #pragma unroll
                for (int j = 0; j < 2; j++) {
                    l0[i][j] += qv[i] * i0v[j];
                    l1[i][j] += qv[i] * i1v[j];
                    d0[i][j] += uv[i] * i0v[j];
                    d1[i][j] += uv[i] * i1v[j];
                }
        }
        __syncthreads();
    }

    const float scale = 0.125f;
    #pragma unroll
    for (int i = 0; i < 4; i++) {
        int gu = ub + ty * 4 + i;
        #pragma unroll
        for (int j = 0; j < 2; j++) {
            int gp = pb + tx * 2 + j;
            if (gp < P_N) {
                float z  = (l0[i][j] - l1[i][j]) * scale;
                float a0 = 1.f / (1.f + expf(-z));
                scores[gu * P_N + gp] = a0 * d0[i][j] + (1.f - a0) * d1[i][j];
            }
        }
    }
}

// ---------------- launch -----------------------------------------------------
extern "C" void kernel_launch(void* const* d_in, const int* in_sizes, int n_in,
                              void* d_out, int out_size)
{
    const float* A_up = (const float*)d_in[0];
    const float* A_gu = (const float*)d_in[1];
    const float* A_gp = (const float*)d_in[2];
    const float* ue   = (const float*)d_in[3];
    const float* pe   = (const float*)d_in[4];
    const float* ge   = (const float*)d_in[5];
    const float* W    = (const float*)d_in[6];
    const int*   uids = (const int*)d_in[7];
    float* out = (float*)d_out;

    float *pXup, *pXgu, *pXgp, *pRup, *pRgu, *pRgp, *pdeg;
    cudaGetSymbolAddress((void**)&pXup, g_Xup);
    cudaGetSymbolAddress((void**)&pXgu, g_Xgu);
    cudaGetSymbolAddress((void**)&pXgp, g_Xgp);
    cudaGetSymbolAddress((void**)&pRup, g_Rup);
    cudaGetSymbolAddress((void**)&pRgu, g_Rgu);
    cudaGetSymbolAddress((void**)&pRgp, g_Rgp);
    cudaGetSymbolAddress((void**)&pdeg, g_deg);

    static bool attr_set = false;
    if (!attr_set) {
        cudaFuncSetAttribute(gemm_all, cudaFuncAttributeMaxDynamicSharedMemorySize, SMEM_BYTES);
        attr_set = true;
    }

    const int n1 = NUP * D;
    zero_bufs<<<(n1 + 255) / 256, 256>>>();
    build_x<<<(n1 + 255) / 256, 256>>>(ue, pe, ge);

    gemm_all<<<NBLK, 256, SMEM_BYTES>>>(A_up, A_gu, A_gp,
                                        pXup, pXgu, pXgp,
                                        pRup, pRgu, pRgp,
                                        pdeg);

    epilogue<<<(NUP * D + 255) / 256, 256>>>(pXup, pRup, pdeg, NUP);
    epilogue<<<(NGU * D + 255) / 256, 256>>>(pXgu, pRgu, pdeg + NUP, NGU);
    epilogue<<<(NGP * D + 255) / 256, 256>>>(pXgp, pRgp, pdeg + NUP + NGU, NGP);

    uf_q_kernel<<<B_N, D>>>(uids, W, out + (size_t)B_N * P_N);

    dim3 sg((P_N + SBP - 1) / SBP, B_N / SBU);
    score_kernel<<<sg, 256>>>(out);
}